// round 9
// baseline (speedup 1.0000x reference)
#include <cuda_runtime.h>
#include <cuda_pipeline.h>

// ---------------- problem dims (fixed by the dataset) ----------------
#define BATCH   2
#define C_IN    256
#define HH      40
#define WW      40
#define CMID    64     // compressed channels
#define CK      100    // k2 * S^2 encoder output channels
#define KK      25     // k2
#define HPAD    44     // xT padded (halo 2)
#define CPH     42     // comp padded (halo 1)
#define PSTRIDE (BATCH * CPH * CPH * CMID)   // one K-partial buffer (225792 floats)

typedef unsigned long long u64;

__device__ __forceinline__ u64 dup2f(float x) {
    u64 r; asm("mov.b64 %0,{%1,%1};" : "=l"(r) : "f"(x)); return r;
}
__device__ __forceinline__ void fma2(u64& d, u64 a, u64 b) {
    asm("fma.rn.f32x2 %0,%1,%2,%0;" : "+l"(d) : "l"(a), "l"(b));
}

// ---------------- scratch (zero-initialized at module load; halos stay 0) ----------------
__device__ __align__(16) float  g_xT   [BATCH * HPAD * HPAD * C_IN];  // x NHWC, 2-px zero halo
__device__ __align__(16) float  g_compP[4 * PSTRIDE];                 // 4 K-split partials, halo 1
__device__ __align__(16) float  g_wt   [9 * CMID * CK];               // w_enc [tap][ci][o]
__device__ __align__(16) float  g_wc   [C_IN * CMID];                 // w_comp [c][o]
__device__ __align__(16) float4 g_soft [BATCH * HH * WW * KK];        // softmax wts [b][p][k]{d}

// ---------------- K0: weight transposes ----------------
__global__ void K0_prep(const float* __restrict__ wcomp,
                        const float* __restrict__ wenc) {
    int i = blockIdx.x * 256 + threadIdx.x;
    if (i < C_IN * CMID) {                    // g_wc[c][o] = wcomp[o][c]
        int c = i >> 6, o = i & 63;
        g_wc[i] = wcomp[o * C_IN + c];
    }
    int j = i - C_IN * CMID;
    if (j >= 0 && j < 9 * CMID * CK) {        // g_wt[tap][ci][o] = wenc[o][ci][tap]
        int tap = j / (CMID * CK);
        int r   = j % (CMID * CK);
        int ci  = r / CK;
        int o   = r % CK;
        g_wt[j] = wenc[o * (CMID * 9) + ci * 9 + tap];
    }
}

// ---------------- K1: fused x-transpose + 1x1-GEMM K-partial ----------------
// 400 blocks = (kc 0..3) x (100 px-tiles) ; 256 threads.
// Block: load x[64ch x 32px] tile -> smem; emit transpose to g_xT; GEMM 32px x 64o
// over its 64 K-channels -> g_compP[kc].
__global__ void __launch_bounds__(256) K1_xpose_gemm(const float* __restrict__ x) {
    __shared__ float xs[64 * 33];
    __shared__ float ws[64 * 64];

    const int t   = threadIdx.x;
    const int blk = blockIdx.x;
    const int pxg = blk % 100;
    const int kc  = blk / 100;
    const int b   = pxg / 50;
    const int p0  = (pxg % 50) * 32;
    const int c0  = kc * 64;

    // weights chunk [64c][64o] via cp.async (contiguous in g_wc)
    {
        const float4* src = (const float4*)(g_wc + c0 * CMID);
        float4* dst = (float4*)ws;
        #pragma unroll
        for (int r = 0; r < 4; r++)
            __pipeline_memcpy_async(&dst[t + r * 256], &src[t + r * 256], 16);
        __pipeline_commit();
    }
    // x tile [64ch][32px], coalesced along px
    #pragma unroll
    for (int r = 0; r < 8; r++) {
        int idx = t + r * 256;
        int cl = idx >> 5, pl = idx & 31;
        xs[cl * 33 + pl] = x[((size_t)(b * C_IN) + c0 + cl) * (HH * WW) + p0 + pl];
    }
    __pipeline_wait_prior(0);
    __syncthreads();

    // transpose out (coalesced along channels)
    #pragma unroll
    for (int r = 0; r < 8; r++) {
        int idx = t + r * 256;
        int cl = idx & 63, pl = idx >> 6;
        int px = p0 + pl;
        int hs = px / WW, wsc = px % WW;
        g_xT[((size_t)(b * HPAD + hs + 2) * HPAD + (wsc + 2)) * C_IN + c0 + cl] =
            xs[cl * 33 + pl];
    }

    // GEMM: thread = (px = t&31, og = t>>5 -> 8 outs)
    const int px = t & 31;
    const int o0 = (t >> 5) << 3;
    u64 acc0 = 0, acc1 = 0, acc2 = 0, acc3 = 0;
    #pragma unroll 8
    for (int c = 0; c < 64; c++) {
        u64 xx = dup2f(xs[c * 33 + px]);
        ulonglong2 wA = *(const ulonglong2*)&ws[c * 64 + o0];
        ulonglong2 wB = *(const ulonglong2*)&ws[c * 64 + o0 + 4];
        fma2(acc0, xx, wA.x); fma2(acc1, xx, wA.y);
        fma2(acc2, xx, wB.x); fma2(acc3, xx, wB.y);
    }
    const int pix = p0 + px;
    const int hs = pix / WW, wsc = pix % WW;
    float* dst = &g_compP[(size_t)kc * PSTRIDE +
                          ((size_t)(b * CPH + hs + 1) * CPH + (wsc + 1)) * CMID + o0];
    *(ulonglong2*)(dst)     = make_ulonglong2(acc0, acc1);
    *(ulonglong2*)(dst + 4) = make_ulonglong2(acc2, acc3);
}

// ---------------- K2: 3x3 encoder conv (100 ch) + fused softmax ----------------
// 160 blocks = b(2) x rowpair(20) x colseg(4); 256 threads.
// comp tile = sum of 4 K-partials; weights double-buffered in smem per tap.
#define CS_STRIDE 66
#define K2_WBUF   6400
// dyn smem floats: 2*6400 (wbuf) + 48*66 (comp) + 2000 (logits) + 2000 (f4 ss)
#define K2_SMEM_FLOATS (2 * K2_WBUF + 48 * CS_STRIDE + 2000 + 2000)
#define K2_SMEM_BYTES  (K2_SMEM_FLOATS * (int)sizeof(float))

__global__ void __launch_bounds__(256) K2_encoder() {
    extern __shared__ float smK2[];
    float*  wbuf   = smK2;                              // [2][6400]
    float*  comp_s = smK2 + 2 * K2_WBUF;                // [48 px][66]
    float*  kk     = comp_s + 48 * CS_STRIDE;           // [20 px][100]
    float4* ss     = (float4*)(kk + 2000);              // [20 pl][25]

    const int t    = threadIdx.x;
    const int blk  = blockIdx.x;
    const int b    = blk / 80;
    const int rem  = blk % 80;
    const int r0   = (rem / 4) * 2;             // kern rows r0, r0+1
    const int cs0  = (rem % 4) * 10;            // kern cols cs0..cs0+9

    // preload tap 0 weights
    {
        const float4* src = (const float4*)g_wt;
        float4* dst = (float4*)wbuf;
        for (int f = t; f < 1600; f += 256)
            __pipeline_memcpy_async(&dst[f], &src[f], 16);
        __pipeline_commit();
    }
    // comp tile: sum of 4 partials, rows r0..r0+3, cols cs0..cs0+11
    #pragma unroll
    for (int r = 0; r < 6; r++) {
        int i  = t + r * 256;
        int px = i >> 5, c2 = i & 31;
        int dr = px / 12, dc = px % 12;
        size_t base = ((size_t)(b * CPH + r0 + dr) * CPH + cs0 + dc) * CMID + c2 * 2;
        float2 v0 = *(const float2*)&g_compP[base];
        float2 v1 = *(const float2*)&g_compP[PSTRIDE + base];
        float2 v2 = *(const float2*)&g_compP[2 * (size_t)PSTRIDE + base];
        float2 v3 = *(const float2*)&g_compP[3 * (size_t)PSTRIDE + base];
        float2 s;
        s.x = (v0.x + v1.x) + (v2.x + v3.x);
        s.y = (v0.y + v1.y) + (v2.y + v3.y);
        *(float2*)&comp_s[px * CS_STRIDE + c2 * 2] = s;
    }

    const int og = t / 5;                       // 0..51 (active < 50)
    const int cp = t % 5;
    u64 a00 = 0, a01 = 0, a10 = 0, a11 = 0;

    for (int tap = 0; tap < 9; tap++) {
        if (tap < 8) {
            float4* dst = (float4*)(wbuf + ((tap + 1) & 1) * K2_WBUF);
            const float4* src = (const float4*)(g_wt + (tap + 1) * K2_WBUF);
            for (int f = t; f < 1600; f += 256)
                __pipeline_memcpy_async(&dst[f], &src[f], 16);
            __pipeline_commit();
            __pipeline_wait_prior(1);
        } else {
            __pipeline_wait_prior(0);
        }
        __syncthreads();

        if (og < 50) {
            const float* wt = wbuf + (tap & 1) * K2_WBUF + og * 2;
            const float* xb = &comp_s[((tap / 3) * 12 + 2 * cp + (tap % 3)) * CS_STRIDE];
            #pragma unroll 8
            for (int ci = 0; ci < CMID; ci += 2) {
                float2 x00 = *(const float2*)&xb[ci];
                float2 x01 = *(const float2*)&xb[CS_STRIDE + ci];
                float2 x10 = *(const float2*)&xb[12 * CS_STRIDE + ci];
                float2 x11 = *(const float2*)&xb[13 * CS_STRIDE + ci];
                u64 w0 = *(const u64*)&wt[ci * CK];
                u64 w1 = *(const u64*)&wt[ci * CK + CK];
                fma2(a00, dup2f(x00.x), w0); fma2(a01, dup2f(x01.x), w0);
                fma2(a10, dup2f(x10.x), w0); fma2(a11, dup2f(x11.x), w0);
                fma2(a00, dup2f(x00.y), w1); fma2(a01, dup2f(x01.y), w1);
                fma2(a10, dup2f(x10.y), w1); fma2(a11, dup2f(x11.y), w1);
            }
        }
        __syncthreads();
    }

    if (og < 50) {                              // stage logits: px = dr*10 + col
        *(u64*)&kk[(2 * cp)      * CK + 2 * og] = a00;
        *(u64*)&kk[(2 * cp + 1)  * CK + 2 * og] = a01;
        *(u64*)&kk[(10 + 2 * cp) * CK + 2 * og] = a10;
        *(u64*)&kk[(11 + 2 * cp) * CK + 2 * og] = a11;
    }
    __syncthreads();

    // ---- 80 softmaxes: (20 kern px) x (sh, sw) ----
    const int wid = t >> 5, lane = t & 31;
    for (int s = wid; s < 80; s += 8) {
        const int px = s >> 2, q = s & 3;
        const int sh = q >> 1, sw = q & 1;
        const int dr = px / 10, wk = cs0 + px % 10;
        float v = -3.0e38f;
        if (lane < KK)
            v = kk[px * CK + lane * 4 + sh * 2 + sw];
        float m = v;
        #pragma unroll
        for (int off = 16; off; off >>= 1)
            m = fmaxf(m, __shfl_xor_sync(0xffffffffu, m, off));
        float e = (lane < KK) ? __expf(v - m) : 0.f;
        float su = e;
        #pragma unroll
        for (int off = 16; off; off >>= 1)
            su += __shfl_xor_sync(0xffffffffu, su, off);
        const int pl = (2 * dr + sh) * 5 + ((wk >> 1) - (cs0 >> 1));
        const int d  = 2 * (wk & 1) + sw;
        if (lane < KK)
            ((float*)&ss[pl * KK + lane])[d] = e / su;
    }
    __syncthreads();

    // ---- store g_soft: 500 f4, coalesced ----
    #pragma unroll
    for (int r = 0; r < 2; r++) {
        int f = t + r * 256;
        if (f < 500) {
            int pl = f / KK, k = f % KK;
            int hu = 2 * r0 + pl / 5;
            int p  = 20 * hu + (cs0 >> 1) + pl % 5;
            g_soft[((size_t)b * (HH * WW) + p) * KK + k] = ss[f];
        }
    }
}

// ---------------- K3: reassembly, row-block (one output row per channel) ----------------
// 160 blocks = b(2) x hsrc(40) x half(2); 256 threads (thread = channel).
// Block serves source px p0..p0+19 (one hu); out[ch][hu][0..79] contiguous per ch.
#define XW_FLOATS (5 * 24 * C_IN)     // 30720
#define ST_ROW    84
#define K3_SMEM_BYTES ((XW_FLOATS + 2000 + 256 * ST_ROW) * (int)sizeof(float))

__global__ void __launch_bounds__(256) K3_reassemble(float* __restrict__ out) {
    extern __shared__ float smK3[];
    float*  xw = smK3;                          // [5 rows][24 cols * 256 ch]
    float4* sk = (float4*)(smK3 + XW_FLOATS);   // [20 px][25 k]
    float*  st = smK3 + XW_FLOATS + 2000;       // [256 ch][84]

    const int t   = threadIdx.x;
    const int blk = blockIdx.x;
    const int b    = blk / 80;
    const int rem  = blk % 80;
    const int hsrc = rem >> 1;
    const int half = rem & 1;
    const int ws0  = half * 20;
    const int hu   = 2 * hsrc + half;
    const int p0   = hsrc * WW + ws0;

    // x window: 5 rows x 24 cols x 256 ch (each row contiguous in g_xT)
    {
        const float4* xsrc = (const float4*)&g_xT[((size_t)(b * HPAD + hsrc) * HPAD + ws0) * C_IN];
        float4* xdst = (float4*)xw;
        for (int f = t; f < XW_FLOATS / 4; f += 256) {
            int row = f / 1536, c = f % 1536;
            __pipeline_memcpy_async(&xdst[row * 1536 + c], &xsrc[row * (HPAD * C_IN / 4) + c], 16);
        }
    }
    // softmax weights: 500 contiguous f4
    for (int f = t; f < 500; f += 256)
        __pipeline_memcpy_async(&sk[f], &g_soft[((size_t)b * (HH * WW) + p0) * KK + f], 16);
    __pipeline_commit();
    __pipeline_wait_prior(0);
    __syncthreads();

    const int ch = t;
    for (int i = 0; i < 20; i++) {
        const ulonglong2* skp = (const ulonglong2*)&sk[i * KK];
        const float* xbase = xw + i * C_IN + ch;
        u64 a01 = 0, a23 = 0;
        #pragma unroll
        for (int k = 0; k < 25; k++) {
            float xv = xbase[(k / 5) * (24 * C_IN) + (k % 5) * C_IN];
            ulonglong2 w = skp[k];
            u64 xx = dup2f(xv);
            fma2(a01, xx, w.x);
            fma2(a23, xx, w.y);
        }
        *(u64*)&st[ch * ST_ROW + 4 * i]     = a01;
        *(u64*)&st[ch * ST_ROW + 4 * i + 2] = a23;
    }
    __syncthreads();

    // coalesced store: out[b][c][hu][0..79] per channel
    const size_t obase = ((size_t)(b * C_IN) * (2 * HH) + hu) * (2 * WW);
    #pragma unroll
    for (int j = 0; j < 20; j++) {
        int f  = t + j * 256;
        int c  = f / 20, w4 = f % 20;
        float4 v = *(const float4*)&st[c * ST_ROW + w4 * 4];
        *(float4*)&out[obase + (size_t)c * (4 * HH * WW) + w4 * 4] = v;
    }
}

// ---------------- launch ----------------
extern "C" void kernel_launch(void* const* d_in, const int* in_sizes, int n_in,
                              void* d_out, int out_size) {
    const float* x     = (const float*)d_in[0];
    const float* wcomp = (const float*)d_in[1];
    const float* wenc  = (const float*)d_in[2];
    float* out = (float*)d_out;

    cudaFuncSetAttribute(K2_encoder,
                         cudaFuncAttributeMaxDynamicSharedMemorySize, K2_SMEM_BYTES);
    cudaFuncSetAttribute(K3_reassemble,
                         cudaFuncAttributeMaxDynamicSharedMemorySize, K3_SMEM_BYTES);

    K0_prep<<<(C_IN * CMID + 9 * CMID * CK + 255) / 256, 256>>>(wcomp, wenc);
    K1_xpose_gemm<<<400, 256>>>(x);
    K2_encoder<<<160, 256, K2_SMEM_BYTES>>>();
    K3_reassemble<<<160, 256, K3_SMEM_BYTES>>>(out);
}